// round 15
// baseline (speedup 1.0000x reference)
#include <cuda_runtime.h>
#include <cuda_fp16.h>
#include <cuda_bf16.h>

// Problem constants (from reference_code)
#define N_PATHS  10000000
#define MAX_LEN  3
#define N_NODES  100000
#define HIDDEN   128

#define PROJ_BLOCKS   592     // 4 CTAs/SM: saturates DRAM, leaves slots free
#define PROJ_THREADS  256

// fp16 planar projection table: g_t16[l * N_NODES + node], 600 KB total.
__device__ __half g_t16[3 * N_NODES];

// ---------------------------------------------------------------------------
// Kernel 1: proj[l][node] = dot(feature[node], W[l][0]) -> fp16 planar table.
// 4 lanes per node, grid-strided on a PARTIAL grid (4 CTAs/SM) so gather
// wave-0 blocks can co-reside under PDL and preload during proj.
// DRAM-bound: 51.2 MB ~ 8 us.
// ---------------------------------------------------------------------------
__global__ void __launch_bounds__(PROJ_THREADS)
proj_kernel(const float* __restrict__ nf, const float* __restrict__ W) {
    const int lane = threadIdx.x & 31;
    const int sub  = lane & 3;     // float4 slot within the node's 64B chunk
    const int gidx = blockIdx.x * blockDim.x + threadIdx.x;
    const int grp  = gidx >> 2;                     // 4-lane group id
    const int ngrp = (PROJ_BLOCKS * PROJ_THREADS) >> 2;

    const float4* w4 = (const float4*)W;

    for (int node = grp; node < N_NODES; node += ngrp) {
        const float4* nf4 = ((const float4*)nf) + (size_t)node * 32 + sub;

        float s0 = 0.0f, s1 = 0.0f, s2 = 0.0f;
        #pragma unroll
        for (int k = 0; k < 8; k++) {
            const float4 f = __ldcs(nf4 + 4 * k);
            const float4 a = __ldg(w4 + 0  + sub + 4 * k);
            const float4 b = __ldg(w4 + 32 + sub + 4 * k);
            const float4 c = __ldg(w4 + 64 + sub + 4 * k);
            s0 += f.x * a.x + f.y * a.y + f.z * a.z + f.w * a.w;
            s1 += f.x * b.x + f.y * b.y + f.z * b.z + f.w * b.w;
            s2 += f.x * c.x + f.y * c.y + f.z * c.z + f.w * c.w;
        }

        s0 += __shfl_xor_sync(0xFFFFFFFFu, s0, 1);
        s1 += __shfl_xor_sync(0xFFFFFFFFu, s1, 1);
        s2 += __shfl_xor_sync(0xFFFFFFFFu, s2, 1);
        s0 += __shfl_xor_sync(0xFFFFFFFFu, s0, 2);
        s1 += __shfl_xor_sync(0xFFFFFFFFu, s1, 2);
        s2 += __shfl_xor_sync(0xFFFFFFFFu, s2, 2);

        if (sub == 0) {
            g_t16[0 * N_NODES + node] = __float2half(s0);
            g_t16[1 * N_NODES + node] = __float2half(s1);
            g_t16[2 * N_NODES + node] = __float2half(s2);
        }
    }
}

// Protected R7 gather body for one quad of paths.
__device__ __forceinline__ void process_quad(const int idx[12], float4* res) {
    float* r = (float*)res;
    #pragma unroll
    for (int k = 0; k < 4; k++) {
        float s = 0.0f;
        int   cnt = 0;
        #pragma unroll
        for (int l = 0; l < 3; l++) {
            const int p = idx[k * 3 + l];
            if (p >= 0) {                     // predicated LDG + SEL (no branch)
                s += __half2float(g_t16[l * N_NODES + p]);
                cnt++;
            }
        }
        float inv = (cnt == 3) ? (1.0f / 3.0f)
                               : ((cnt == 2) ? 0.5f : 1.0f);
        r[k] = s * inv;
    }
}

// ---------------------------------------------------------------------------
// Kernel 2: gather + masked mean, PDL, TWO quads per thread.
// Both quads' paths (96 B/thread) are streamed in BEFORE the dependency
// sync, so wave-0 overlaps proj with twice R13's preload traffic; blocks
// still flow in many waves (no full-machine parking, unlike R14).
// Per-quad inner loop identical to the floor-proven R7 code.
// ---------------------------------------------------------------------------
__global__ void __launch_bounds__(256)
gather_kernel(const int* __restrict__ paths, float* __restrict__ out) {
    const long long HT = N_PATHS / 8;   // 1.25M thread-slots (2 quads each)
    const long long t  = (long long)blockIdx.x * blockDim.x + threadIdx.x;
    if (t >= HT) return;

    const long long qa = t * 2;
    const long long qb = qa + 1;

    // Pre-dependency: stream in both quads' paths (independent of proj)
    const int4* pa = ((const int4*)paths) + qa * 3;
    int4 a0 = __ldcs(pa + 0);
    int4 a1 = __ldcs(pa + 1);
    int4 a2 = __ldcs(pa + 2);
    int4 b0 = __ldcs(pa + 3);
    int4 b1 = __ldcs(pa + 4);
    int4 b2 = __ldcs(pa + 5);

    cudaGridDependencySynchronize();   // proj table complete + visible

    {
        const int idx[12] = { a0.x, a0.y, a0.z, a0.w,
                              a1.x, a1.y, a1.z, a1.w,
                              a2.x, a2.y, a2.z, a2.w };
        float4 res;
        process_quad(idx, &res);
        __stcs(((float4*)out) + qa, res);
    }
    {
        const int idx[12] = { b0.x, b0.y, b0.z, b0.w,
                              b1.x, b1.y, b1.z, b1.w,
                              b2.x, b2.y, b2.z, b2.w };
        float4 res;
        process_quad(idx, &res);
        __stcs(((float4*)out) + qb, res);
    }
}

// ---------------------------------------------------------------------------
// Launch. Inputs identified by element count:
//   30,000,000 -> paths (int32 [10M,3]); 12,800,000 -> node_feature; 384 -> W
// ---------------------------------------------------------------------------
extern "C" void kernel_launch(void* const* d_in, const int* in_sizes, int n_in,
                              void* d_out, int out_size) {
    const void*  paths_raw = nullptr;
    const float* nf        = nullptr;
    const float* W         = nullptr;

    for (int i = 0; i < n_in; i++) {
        if      (in_sizes[i] == N_PATHS * MAX_LEN)  paths_raw = d_in[i];
        else if (in_sizes[i] == N_NODES * HIDDEN)   nf        = (const float*)d_in[i];
        else if (in_sizes[i] == MAX_LEN * HIDDEN)   W         = (const float*)d_in[i];
    }

    float* out = (float*)d_out;

    // proj: partial grid (4 CTAs/SM), grid-strided
    proj_kernel<<<PROJ_BLOCKS, PROJ_THREADS>>>(nf, W);

    // gather with PDL: 1.25M threads, 2 quads each -> 4883 blocks of 256
    {
        const int threads = 256;
        const long long nThreads = N_PATHS / 8;
        const int blocks = (int)((nThreads + threads - 1) / threads);

        cudaLaunchAttribute attrs[1];
        attrs[0].id = cudaLaunchAttributeProgrammaticStreamSerialization;
        attrs[0].val.programmaticStreamSerializationAllowed = 1;

        cudaLaunchConfig_t cfg = {};
        cfg.gridDim  = dim3((unsigned)blocks, 1, 1);
        cfg.blockDim = dim3((unsigned)threads, 1, 1);
        cfg.dynamicSmemBytes = 0;
        cfg.stream   = 0;
        cfg.attrs    = attrs;
        cfg.numAttrs = 1;

        cudaLaunchKernelEx(&cfg, gather_kernel,
                           (const int*)paths_raw, out);
    }
}

// round 16
// speedup vs baseline: 1.1118x; 1.1118x over previous
#include <cuda_runtime.h>
#include <cuda_fp16.h>
#include <cuda_bf16.h>

// Problem constants (from reference_code)
#define N_PATHS  10000000
#define MAX_LEN  3
#define N_NODES  100000
#define HIDDEN   128

// fp16 planar projection table: g_t16[l * N_NODES + node], 600 KB total.
__device__ __half g_t16[3 * N_NODES];

// ---------------------------------------------------------------------------
// Kernel 1: proj[l][node] = dot(feature[node], W[l][0]) -> fp16 planar table.
// R12/R13 body (4 lanes/node, 8 nodes/warp, 2-level shuffle reduce).
// After the table stores, each thread fires the PDL trigger so the dependent
// gather's cudaGridDependencySynchronize() releases at trigger (with implicit
// memory flush) instead of waiting for full grid drain.
// ---------------------------------------------------------------------------
__global__ void __launch_bounds__(256)
proj_kernel(const float* __restrict__ nf, const float* __restrict__ W) {
    const int lane   = threadIdx.x & 31;
    const int sub    = lane & 3;
    const int nin    = lane >> 2;
    const int warpId = (blockIdx.x * blockDim.x + threadIdx.x) >> 5;
    const int node   = warpId * 8 + nin;

    if (node < N_NODES) {
        const float4* nf4 = ((const float4*)nf) + (size_t)node * 32 + sub;
        const float4* w4  = (const float4*)W;

        float s0 = 0.0f, s1 = 0.0f, s2 = 0.0f;
        #pragma unroll
        for (int k = 0; k < 8; k++) {
            const float4 f = __ldcs(nf4 + 4 * k);
            const float4 a = __ldg(w4 + 0  + sub + 4 * k);
            const float4 b = __ldg(w4 + 32 + sub + 4 * k);
            const float4 c = __ldg(w4 + 64 + sub + 4 * k);
            s0 += f.x * a.x + f.y * a.y + f.z * a.z + f.w * a.w;
            s1 += f.x * b.x + f.y * b.y + f.z * b.z + f.w * b.w;
            s2 += f.x * c.x + f.y * c.y + f.z * c.z + f.w * c.w;
        }

        s0 += __shfl_xor_sync(0xFFFFFFFFu, s0, 1);
        s1 += __shfl_xor_sync(0xFFFFFFFFu, s1, 1);
        s2 += __shfl_xor_sync(0xFFFFFFFFu, s2, 1);
        s0 += __shfl_xor_sync(0xFFFFFFFFu, s0, 2);
        s1 += __shfl_xor_sync(0xFFFFFFFFu, s1, 2);
        s2 += __shfl_xor_sync(0xFFFFFFFFu, s2, 2);

        if (sub == 0) {
            g_t16[0 * N_NODES + node] = __float2half(s0);
            g_t16[1 * N_NODES + node] = __float2half(s1);
            g_t16[2 * N_NODES + node] = __float2half(s2);
        }
    }

    // Release the dependent gather early (stores above are flushed by the
    // trigger's implicit memory flush).
    cudaTriggerProgrammaticLaunchCompletion();
}

// ---------------------------------------------------------------------------
// Kernel 2: gather + masked mean, PDL. BYTE-IDENTICAL to the measured-best
// R13 kernel (gather at the 30M-wavefront L1tex floor, ~100 us; protected).
// Paths are loaded BEFORE cudaGridDependencySynchronize() so wave-0's ramp
// and paths traffic overlap proj execution.
// ---------------------------------------------------------------------------
__global__ void __launch_bounds__(256)
gather_kernel(const int* __restrict__ paths, float* __restrict__ out) {
    const long long tid = (long long)blockIdx.x * blockDim.x + threadIdx.x;
    if (tid >= (N_PATHS / 4)) return;

    // Pre-dependency work: stream in this thread's 4 paths (48 B)
    const int4* p4 = ((const int4*)paths) + tid * 3;
    int4 v0 = __ldcs(p4 + 0);
    int4 v1 = __ldcs(p4 + 1);
    int4 v2 = __ldcs(p4 + 2);

    // Wait for proj_kernel trigger (PDL); table stores visible after.
    cudaGridDependencySynchronize();

    int idx[12] = { v0.x, v0.y, v0.z, v0.w,
                    v1.x, v1.y, v1.z, v1.w,
                    v2.x, v2.y, v2.z, v2.w };

    float4 res;
    float* r = (float*)&res;

    #pragma unroll
    for (int k = 0; k < 4; k++) {
        float s = 0.0f;
        int   cnt = 0;
        #pragma unroll
        for (int l = 0; l < 3; l++) {
            const int p = idx[k * 3 + l];
            if (p >= 0) {                     // predicated LDG + SEL (no branch)
                s += __half2float(g_t16[l * N_NODES + p]);
                cnt++;
            }
        }
        float inv = (cnt == 3) ? (1.0f / 3.0f)
                               : ((cnt == 2) ? 0.5f : 1.0f);
        r[k] = s * inv;
    }

    __stcs(((float4*)out) + tid, res);
}

// ---------------------------------------------------------------------------
// Launch. Inputs identified by element count:
//   30,000,000 -> paths (int32 [10M,3]); 12,800,000 -> node_feature; 384 -> W
// ---------------------------------------------------------------------------
extern "C" void kernel_launch(void* const* d_in, const int* in_sizes, int n_in,
                              void* d_out, int out_size) {
    const void*  paths_raw = nullptr;
    const float* nf        = nullptr;
    const float* W         = nullptr;

    for (int i = 0; i < n_in; i++) {
        if      (in_sizes[i] == N_PATHS * MAX_LEN)  paths_raw = d_in[i];
        else if (in_sizes[i] == N_NODES * HIDDEN)   nf        = (const float*)d_in[i];
        else if (in_sizes[i] == MAX_LEN * HIDDEN)   W         = (const float*)d_in[i];
    }

    float* out = (float*)d_out;

    // proj: 8 nodes per warp -> 12500 warps -> 1563 blocks of 256
    {
        const int threads = 256;
        const int warps   = (N_NODES + 7) / 8;
        const int blocks  = (warps * 32 + threads - 1) / threads;
        proj_kernel<<<blocks, threads>>>(nf, W);
    }

    // gather with PDL: 9766 blocks of 256, 1 quad per thread (R13 shape)
    {
        const int threads = 256;
        const long long nThreads = N_PATHS / 4;
        const int blocks = (int)((nThreads + threads - 1) / threads);

        cudaLaunchAttribute attrs[1];
        attrs[0].id = cudaLaunchAttributeProgrammaticStreamSerialization;
        attrs[0].val.programmaticStreamSerializationAllowed = 1;

        cudaLaunchConfig_t cfg = {};
        cfg.gridDim  = dim3((unsigned)blocks, 1, 1);
        cfg.blockDim = dim3((unsigned)threads, 1, 1);
        cfg.dynamicSmemBytes = 0;
        cfg.stream   = 0;
        cfg.attrs    = attrs;
        cfg.numAttrs = 1;

        cudaLaunchKernelEx(&cfg, gather_kernel,
                           (const int*)paths_raw, out);
    }
}

// round 17
// speedup vs baseline: 1.1140x; 1.0020x over previous
#include <cuda_runtime.h>
#include <cuda_fp16.h>
#include <cuda_bf16.h>

// Problem constants (from reference_code)
#define N_PATHS  10000000
#define MAX_LEN  3
#define N_NODES  100000
#define HIDDEN   128

// fp16 planar projection table: g_t16[l * N_NODES + node], 600 KB total.
__device__ __half g_t16[3 * N_NODES];

// ---------------------------------------------------------------------------
// Kernel 1: proj[l][node] = dot(feature[node], W[l][0]) -> fp16 planar table.
// R16 body (4 lanes/node, 8 nodes/warp, 2-level shuffle reduce) + PDL
// trigger so the dependent gather releases at trigger, not grid drain.
// ---------------------------------------------------------------------------
__global__ void __launch_bounds__(256)
proj_kernel(const float* __restrict__ nf, const float* __restrict__ W) {
    const int lane   = threadIdx.x & 31;
    const int sub    = lane & 3;
    const int nin    = lane >> 2;
    const int warpId = (blockIdx.x * blockDim.x + threadIdx.x) >> 5;
    const int node   = warpId * 8 + nin;

    if (node < N_NODES) {
        const float4* nf4 = ((const float4*)nf) + (size_t)node * 32 + sub;
        const float4* w4  = (const float4*)W;

        float s0 = 0.0f, s1 = 0.0f, s2 = 0.0f;
        #pragma unroll
        for (int k = 0; k < 8; k++) {
            const float4 f = __ldcs(nf4 + 4 * k);
            const float4 a = __ldg(w4 + 0  + sub + 4 * k);
            const float4 b = __ldg(w4 + 32 + sub + 4 * k);
            const float4 c = __ldg(w4 + 64 + sub + 4 * k);
            s0 += f.x * a.x + f.y * a.y + f.z * a.z + f.w * a.w;
            s1 += f.x * b.x + f.y * b.y + f.z * b.z + f.w * b.w;
            s2 += f.x * c.x + f.y * c.y + f.z * c.z + f.w * c.w;
        }

        s0 += __shfl_xor_sync(0xFFFFFFFFu, s0, 1);
        s1 += __shfl_xor_sync(0xFFFFFFFFu, s1, 1);
        s2 += __shfl_xor_sync(0xFFFFFFFFu, s2, 1);
        s0 += __shfl_xor_sync(0xFFFFFFFFu, s0, 2);
        s1 += __shfl_xor_sync(0xFFFFFFFFu, s1, 2);
        s2 += __shfl_xor_sync(0xFFFFFFFFu, s2, 2);

        if (sub == 0) {
            g_t16[0 * N_NODES + node] = __float2half(s0);
            g_t16[1 * N_NODES + node] = __float2half(s1);
            g_t16[2 * N_NODES + node] = __float2half(s2);
        }
    }

    cudaTriggerProgrammaticLaunchCompletion();
}

// ---------------------------------------------------------------------------
// Kernel 2: gather + masked mean, PDL. Per-thread logic BYTE-IDENTICAL to
// R16 (floor-proven). Only change: 128-thread CTAs (19532 blocks) to halve
// per-CTA front-batched LDG injection into the L1tex queue (lower cross-CTA
// spread per the B300 MLP_p1 model) and shrink wave tails.
// ---------------------------------------------------------------------------
__global__ void __launch_bounds__(128)
gather_kernel(const int* __restrict__ paths, float* __restrict__ out) {
    const long long tid = (long long)blockIdx.x * blockDim.x + threadIdx.x;
    if (tid >= (N_PATHS / 4)) return;

    // Pre-dependency work: stream in this thread's 4 paths (48 B)
    const int4* p4 = ((const int4*)paths) + tid * 3;
    int4 v0 = __ldcs(p4 + 0);
    int4 v1 = __ldcs(p4 + 1);
    int4 v2 = __ldcs(p4 + 2);

    // Wait for proj_kernel trigger (PDL); table stores visible after.
    cudaGridDependencySynchronize();

    int idx[12] = { v0.x, v0.y, v0.z, v0.w,
                    v1.x, v1.y, v1.z, v1.w,
                    v2.x, v2.y, v2.z, v2.w };

    float4 res;
    float* r = (float*)&res;

    #pragma unroll
    for (int k = 0; k < 4; k++) {
        float s = 0.0f;
        int   cnt = 0;
        #pragma unroll
        for (int l = 0; l < 3; l++) {
            const int p = idx[k * 3 + l];
            if (p >= 0) {                     // predicated LDG + SEL (no branch)
                s += __half2float(g_t16[l * N_NODES + p]);
                cnt++;
            }
        }
        float inv = (cnt == 3) ? (1.0f / 3.0f)
                               : ((cnt == 2) ? 0.5f : 1.0f);
        r[k] = s * inv;
    }

    __stcs(((float4*)out) + tid, res);
}

// ---------------------------------------------------------------------------
// Launch. Inputs identified by element count:
//   30,000,000 -> paths (int32 [10M,3]); 12,800,000 -> node_feature; 384 -> W
// ---------------------------------------------------------------------------
extern "C" void kernel_launch(void* const* d_in, const int* in_sizes, int n_in,
                              void* d_out, int out_size) {
    const void*  paths_raw = nullptr;
    const float* nf        = nullptr;
    const float* W         = nullptr;

    for (int i = 0; i < n_in; i++) {
        if      (in_sizes[i] == N_PATHS * MAX_LEN)  paths_raw = d_in[i];
        else if (in_sizes[i] == N_NODES * HIDDEN)   nf        = (const float*)d_in[i];
        else if (in_sizes[i] == MAX_LEN * HIDDEN)   W         = (const float*)d_in[i];
    }

    float* out = (float*)d_out;

    // proj: 8 nodes per warp -> 12500 warps -> 1563 blocks of 256
    {
        const int threads = 256;
        const int warps   = (N_NODES + 7) / 8;
        const int blocks  = (warps * 32 + threads - 1) / threads;
        proj_kernel<<<blocks, threads>>>(nf, W);
    }

    // gather with PDL: 19532 blocks of 128, 1 quad per thread
    {
        const int threads = 128;
        const long long nThreads = N_PATHS / 4;
        const int blocks = (int)((nThreads + threads - 1) / threads);

        cudaLaunchAttribute attrs[1];
        attrs[0].id = cudaLaunchAttributeProgrammaticStreamSerialization;
        attrs[0].val.programmaticStreamSerializationAllowed = 1;

        cudaLaunchConfig_t cfg = {};
        cfg.gridDim  = dim3((unsigned)blocks, 1, 1);
        cfg.blockDim = dim3((unsigned)threads, 1, 1);
        cfg.dynamicSmemBytes = 0;
        cfg.stream   = 0;
        cfg.attrs    = attrs;
        cfg.numAttrs = 1;

        cudaLaunchKernelEx(&cfg, gather_kernel,
                           (const int*)paths_raw, out);
    }
}